// round 1
// baseline (speedup 1.0000x reference)
#include <cuda_runtime.h>
#include <math.h>

// ---------------- problem constants ----------------
#define NB   8
#define NN   4096          // H*W
#define CVD  256
#define CTD  512
#define NT   77
#define NHH  8
#define DH   32
#define TOPM 5
#define ROWS (NB*NN)       // 32768

// ---------------- scratch (device globals; no allocs allowed) ----------------
__device__ float g_x[ROWS*CVD];        // LN1 output
__device__ float g_q[ROWS*CVD];        // q projection (l2-normed in place)
__device__ float g_k[NB*NT*CVD];       // k (l2-normed per head)
__device__ float g_v[NB*NT*CVD];       // v
__device__ int   g_pad[NB*NT];         // pad flags
__device__ float g_aligned[ROWS*CVD];  // attention output
__device__ float g_proj[ROWS*CVD];     // aligned @ Wo + bo
__device__ float g_y2[ROWS*CVD];       // LN2 output (FFN input + residual)
__device__ float g_hdn[ROWS*4*CVD];    // FFN hidden (gelu)

// ---------------- LN1: x = LN(visual, g1, b1) ----------------
__global__ __launch_bounds__(256) void ln1_kernel(const float* __restrict__ in,
                                                  const float* __restrict__ g,
                                                  const float* __restrict__ b) {
    int warp = (blockIdx.x * blockDim.x + threadIdx.x) >> 5;
    int lane = threadIdx.x & 31;
    const float* row = in + (size_t)warp * CVD;
    float v[8]; float s = 0.f, ss = 0.f;
#pragma unroll
    for (int i = 0; i < 8; i++) { v[i] = row[lane*8 + i]; s += v[i]; ss += v[i]*v[i]; }
#pragma unroll
    for (int o = 16; o; o >>= 1) { s += __shfl_xor_sync(~0u, s, o); ss += __shfl_xor_sync(~0u, ss, o); }
    float mu  = s * (1.f/CVD);
    float var = ss * (1.f/CVD) - mu*mu;
    float inv = rsqrtf(var + 1e-5f);
    float* orow = g_x + (size_t)warp * CVD;
#pragma unroll
    for (int i = 0; i < 8; i++) { int c = lane*8 + i; orow[c] = (v[i]-mu)*inv*g[c] + b[c]; }
}

// ---------------- LN2 + residual: y2 = LN(x + alpha*proj, g2, b2) ----------------
__global__ __launch_bounds__(256) void ln2res_kernel(const float* __restrict__ g,
                                                     const float* __restrict__ b,
                                                     const float* __restrict__ alpha_p) {
    int warp = (blockIdx.x * blockDim.x + threadIdx.x) >> 5;
    int lane = threadIdx.x & 31;
    float alpha = alpha_p[0];
    const float* xr = g_x    + (size_t)warp * CVD;
    const float* pr = g_proj + (size_t)warp * CVD;
    float v[8]; float s = 0.f, ss = 0.f;
#pragma unroll
    for (int i = 0; i < 8; i++) {
        int c = lane*8 + i;
        v[i] = xr[c] + alpha * pr[c];
        s += v[i]; ss += v[i]*v[i];
    }
#pragma unroll
    for (int o = 16; o; o >>= 1) { s += __shfl_xor_sync(~0u, s, o); ss += __shfl_xor_sync(~0u, ss, o); }
    float mu  = s * (1.f/CVD);
    float var = ss * (1.f/CVD) - mu*mu;
    float inv = rsqrtf(var + 1e-5f);
    float* orow = g_y2 + (size_t)warp * CVD;
#pragma unroll
    for (int i = 0; i < 8; i++) { int c = lane*8 + i; orow[c] = (v[i]-mu)*inv*g[c] + b[c]; }
}

// ---------------- K/V projection + pad flags + k l2norm (warp == head) ----------------
__global__ __launch_bounds__(256) void kv_kernel(const float* __restrict__ text,
                                                 const float* __restrict__ Wk, const float* __restrict__ bk,
                                                 const float* __restrict__ Wv, const float* __restrict__ bv) {
    int bt = blockIdx.x;          // b*NT + t
    int c  = threadIdx.x;         // output channel
    __shared__ float txt[CTD];
    __shared__ float red[256];
    const float* trow = text + (size_t)bt * CTD;
    txt[c] = trow[c]; txt[c+256] = trow[c+256];
    __syncthreads();
    // pad flag: sum |text| <= 1e-6
    red[c] = fabsf(txt[c]) + fabsf(txt[c+256]);
    __syncthreads();
    for (int s = 128; s; s >>= 1) { if (c < s) red[c] += red[c+s]; __syncthreads(); }
    if (c == 0) g_pad[bt] = (red[0] <= 1e-6f);
    float kc = bk[c], vc = bv[c];
    for (int kk = 0; kk < CTD; kk++) {
        float t = txt[kk];
        kc += t * Wk[kk*CVD + c];
        vc += t * Wv[kk*CVD + c];
    }
    // l2 norm of k over head dim (32 consecutive channels = this warp)
    float ss = kc * kc;
#pragma unroll
    for (int o = 16; o; o >>= 1) ss += __shfl_xor_sync(~0u, ss, o);
    kc /= fmaxf(sqrtf(ss), 1e-6f);
    g_k[(size_t)bt*CVD + c] = kc;
    g_v[(size_t)bt*CVD + c] = vc;
}

// ---------------- l2norm of q per (row, head): warp per head-row ----------------
__global__ __launch_bounds__(256) void qnorm_kernel() {
    int w = (blockIdx.x * blockDim.x + threadIdx.x) >> 5;  // row*NHH + h
    int lane = threadIdx.x & 31;
    size_t idx = (size_t)w * 32 + lane;                    // contiguous: row*256 + h*32 + d
    float v = g_q[idx];
    float ss = v * v;
#pragma unroll
    for (int o = 16; o; o >>= 1) ss += __shfl_xor_sync(~0u, ss, o);
    g_q[idx] = v / fmaxf(sqrtf(ss), 1e-6f);
}

// ---------------- attention: block per (b,n), warp per head ----------------
__global__ __launch_bounds__(256) void attn_kernel(const float* __restrict__ logit_scale) {
    int row = blockIdx.x;           // b*NN + n
    int b   = row >> 12;            // / 4096
    int tid = threadIdx.x;
    int h = tid >> 5, lane = tid & 31;
    __shared__ float qs[CVD];
    __shared__ int   spad[NT];
    qs[tid] = g_q[(size_t)row * CVD + tid];
    if (tid < NT) spad[tid] = g_pad[b*NT + tid];
    __syncthreads();

    float ls = logit_scale[0];
    float scale = expf(fminf(fmaxf(ls, -2.f), 2.f)) * 0.17677669529663687f; // /sqrt(32)

    const float* kb = g_k + (size_t)b * NT * CVD + h * DH;
    float s[3];
#pragma unroll
    for (int i = 0; i < 3; i++) {
        int t = lane + 32*i;
        float sv = -INFINITY;
        if (t < NT && !spad[t]) {
            const float* kr = kb + (size_t)t * CVD;
            float acc = 0.f;
#pragma unroll
            for (int d = 0; d < DH; d++) acc += qs[h*DH + d] * kr[d];
            sv = acc * scale;
        }
        s[i] = sv;
    }

    // top-5 across 77 values (3 per lane), tie -> smaller t (matches lax.top_k)
    float topv[TOPM]; int topt[TOPM];
#pragma unroll
    for (int it = 0; it < TOPM; it++) {
        float bv = s[0]; int bt = lane;
        if (lane + 32 < NT && s[1] > bv) { bv = s[1]; bt = lane + 32; }
        if (lane + 64 < NT && s[2] > bv) { bv = s[2]; bt = lane + 64; }
#pragma unroll
        for (int o = 16; o; o >>= 1) {
            float ov = __shfl_xor_sync(~0u, bv, o);
            int   ot = __shfl_xor_sync(~0u, bt, o);
            if (ov > bv || (ov == bv && ot < bt)) { bv = ov; bt = ot; }
        }
        topv[it] = bv; topt[it] = bt;
        if ((bt & 31) == lane) s[bt >> 5] = -INFINITY;
    }

    float outv = 0.f;
    float m = topv[0];
    if (!(m == -INFINITY)) {       // not all-pad
        float e[TOPM]; float ws = 0.f;
#pragma unroll
        for (int i = 0; i < TOPM; i++) { e[i] = expf(topv[i] - m); ws += e[i]; }
        float inv = 1.f / ws;
        const float* vb = g_v + (size_t)b * NT * CVD + h * DH + lane;
#pragma unroll
        for (int i = 0; i < TOPM; i++) outv += (e[i] * inv) * vb[(size_t)topt[i] * CVD];
    }
    g_aligned[(size_t)row * CVD + h*DH + lane] = outv;
}

// ---------------- generic tiled GEMM: C = A(MxK) @ B(KxN) + bias [; gelu][; +res] ----------------
__global__ __launch_bounds__(256) void gemm_kernel(const float* __restrict__ A,
                                                   const float* __restrict__ B,
                                                   const float* __restrict__ bias,
                                                   const float* __restrict__ res,
                                                   float* __restrict__ C,
                                                   int M, int N, int K, int gelu) {
    __shared__ float As[16][64];   // transposed: As[k][m]
    __shared__ float Bs[16][64];
    int tid = threadIdx.x;
    int tm = tid >> 4, tn = tid & 15;
    int m0 = blockIdx.y * 64, n0 = blockIdx.x * 64;
    float acc[4][4] = {};
    int la_m = tid >> 2, la_k = (tid & 3) * 4;   // A tile loader coords
    int lb_k = tid >> 4, lb_n = (tid & 15) * 4;  // B tile loader coords
    const float* Ap = A + (size_t)(m0 + la_m) * K + la_k;
    const float* Bp = B + (size_t)lb_k * N + n0 + lb_n;
    for (int k0 = 0; k0 < K; k0 += 16) {
        float4 a4 = *(const float4*)(Ap + k0);
        float4 b4 = *(const float4*)(Bp + (size_t)k0 * N);
        As[la_k+0][la_m] = a4.x; As[la_k+1][la_m] = a4.y;
        As[la_k+2][la_m] = a4.z; As[la_k+3][la_m] = a4.w;
        *(float4*)&Bs[lb_k][lb_n] = b4;
        __syncthreads();
#pragma unroll
        for (int k = 0; k < 16; k++) {
            float4 av = *(const float4*)&As[k][tm*4];
            float4 bv = *(const float4*)&Bs[k][tn*4];
            float aa[4] = {av.x, av.y, av.z, av.w};
            float bb[4] = {bv.x, bv.y, bv.z, bv.w};
#pragma unroll
            for (int i = 0; i < 4; i++)
#pragma unroll
                for (int j = 0; j < 4; j++) acc[i][j] += aa[i] * bb[j];
        }
        __syncthreads();
    }
#pragma unroll
    for (int i = 0; i < 4; i++) {
        size_t r = (size_t)(m0 + tm*4 + i);
#pragma unroll
        for (int j = 0; j < 4; j++) {
            int cc = n0 + tn*4 + j;
            float v = acc[i][j] + bias[cc];
            if (gelu) v = 0.5f * v * (1.f + erff(v * 0.70710678118654752f));
            if (res)  v += res[r * N + cc];
            C[r * N + cc] = v;
        }
    }
}

// ---------------- launch ----------------
extern "C" void kernel_launch(void* const* d_in, const int* in_sizes, int n_in,
                              void* d_out, int out_size) {
    const float* vis   = (const float*)d_in[0];
    const float* text  = (const float*)d_in[1];
    const float* Wq    = (const float*)d_in[2];
    const float* bq    = (const float*)d_in[3];
    const float* Wk    = (const float*)d_in[4];
    const float* bk    = (const float*)d_in[5];
    const float* Wv    = (const float*)d_in[6];
    const float* bv    = (const float*)d_in[7];
    const float* Wo    = (const float*)d_in[8];
    const float* bo    = (const float*)d_in[9];
    const float* g1    = (const float*)d_in[10];
    const float* b1    = (const float*)d_in[11];
    const float* g2    = (const float*)d_in[12];
    const float* b2    = (const float*)d_in[13];
    const float* Wf1   = (const float*)d_in[14];
    const float* bf1   = (const float*)d_in[15];
    const float* Wf2   = (const float*)d_in[16];
    const float* bf2   = (const float*)d_in[17];
    const float* ls    = (const float*)d_in[18];
    const float* alpha = (const float*)d_in[19];
    float* out = (float*)d_out;

    float *px, *pq, *paligned, *pproj, *py2, *phdn;
    cudaGetSymbolAddress((void**)&px,       g_x);
    cudaGetSymbolAddress((void**)&pq,       g_q);
    cudaGetSymbolAddress((void**)&paligned, g_aligned);
    cudaGetSymbolAddress((void**)&pproj,    g_proj);
    cudaGetSymbolAddress((void**)&py2,      g_y2);
    cudaGetSymbolAddress((void**)&phdn,     g_hdn);

    // 1) LN1
    ln1_kernel<<<ROWS/8, 256>>>(vis, g1, b1);
    // 2) K/V projection + pad + k-norm
    kv_kernel<<<NB*NT, 256>>>(text, Wk, bk, Wv, bv);
    // 3) q = x @ Wq + bq
    gemm_kernel<<<dim3(CVD/64, ROWS/64), 256>>>(px, Wq, bq, nullptr, pq, ROWS, CVD, CVD, 0);
    // 4) q l2norm per head
    qnorm_kernel<<<ROWS*NHH/8, 256>>>();
    // 5) attention (cosine sim, pad mask, top-5, softmax, AV)
    attn_kernel<<<ROWS, 256>>>(ls);
    // 6) proj = aligned @ Wo + bo
    gemm_kernel<<<dim3(CVD/64, ROWS/64), 256>>>(paligned, Wo, bo, nullptr, pproj, ROWS, CVD, CVD, 0);
    // 7) y2 = LN2(x + alpha*proj)
    ln2res_kernel<<<ROWS/8, 256>>>(g2, b2, alpha);
    // 8) hdn = gelu(y2 @ Wf1 + bf1)
    gemm_kernel<<<dim3(4*CVD/64, ROWS/64), 256>>>(py2, Wf1, bf1, nullptr, phdn, ROWS, 4*CVD, CVD, 1);
    // 9) out = y2 + hdn @ Wf2 + bf2
    gemm_kernel<<<dim3(CVD/64, ROWS/64), 256>>>(phdn, Wf2, bf2, py2, out, ROWS, CVD, 4*CVD, 0);
}

// round 2
// speedup vs baseline: 1.0998x; 1.0998x over previous
#include <cuda_runtime.h>
#include <math.h>
#include <stdint.h>

// ---------------- problem constants ----------------
#define NB   8
#define NN   4096          // H*W
#define CVD  256
#define CTD  512
#define NT   77
#define NHH  8
#define DH   32
#define TOPM 5
#define ROWS (NB*NN)       // 32768

// ---------------- scratch (device globals; no allocs allowed) ----------------
__device__ float g_x[ROWS*CVD];        // LN1 output
__device__ float g_q[ROWS*CVD];        // q projection (l2-normed in epilogue)
__device__ float g_k[NB*NT*CVD];       // k (l2-normed per head)
__device__ float g_v[NB*NT*CVD];       // v
__device__ int   g_pad[NB*NT];         // pad flags
__device__ float g_aligned[ROWS*CVD];  // attention output
__device__ float g_proj[ROWS*CVD];     // aligned @ Wo + bo
__device__ float g_y2[ROWS*CVD];       // LN2 output (FFN input + residual)
__device__ float g_hdn[ROWS*4*CVD];    // FFN hidden (gelu)

// ---------------- LN1 ----------------
__global__ __launch_bounds__(256) void ln1_kernel(const float* __restrict__ in,
                                                  const float* __restrict__ g,
                                                  const float* __restrict__ b) {
    int warp = (blockIdx.x * blockDim.x + threadIdx.x) >> 5;
    int lane = threadIdx.x & 31;
    const float* row = in + (size_t)warp * CVD;
    float v[8]; float s = 0.f, ss = 0.f;
#pragma unroll
    for (int i = 0; i < 8; i++) { v[i] = row[lane*8 + i]; s += v[i]; ss += v[i]*v[i]; }
#pragma unroll
    for (int o = 16; o; o >>= 1) { s += __shfl_xor_sync(~0u, s, o); ss += __shfl_xor_sync(~0u, ss, o); }
    float mu  = s * (1.f/CVD);
    float var = ss * (1.f/CVD) - mu*mu;
    float inv = rsqrtf(var + 1e-5f);
    float* orow = g_x + (size_t)warp * CVD;
#pragma unroll
    for (int i = 0; i < 8; i++) { int c = lane*8 + i; orow[c] = (v[i]-mu)*inv*g[c] + b[c]; }
}

// ---------------- LN2 + residual ----------------
__global__ __launch_bounds__(256) void ln2res_kernel(const float* __restrict__ g,
                                                     const float* __restrict__ b,
                                                     const float* __restrict__ alpha_p) {
    int warp = (blockIdx.x * blockDim.x + threadIdx.x) >> 5;
    int lane = threadIdx.x & 31;
    float alpha = alpha_p[0];
    const float* xr = g_x    + (size_t)warp * CVD;
    const float* pr = g_proj + (size_t)warp * CVD;
    float v[8]; float s = 0.f, ss = 0.f;
#pragma unroll
    for (int i = 0; i < 8; i++) {
        int c = lane*8 + i;
        v[i] = xr[c] + alpha * pr[c];
        s += v[i]; ss += v[i]*v[i];
    }
#pragma unroll
    for (int o = 16; o; o >>= 1) { s += __shfl_xor_sync(~0u, s, o); ss += __shfl_xor_sync(~0u, ss, o); }
    float mu  = s * (1.f/CVD);
    float var = ss * (1.f/CVD) - mu*mu;
    float inv = rsqrtf(var + 1e-5f);
    float* orow = g_y2 + (size_t)warp * CVD;
#pragma unroll
    for (int i = 0; i < 8; i++) { int c = lane*8 + i; orow[c] = (v[i]-mu)*inv*g[c] + b[c]; }
}

// ---------------- K/V projection + pad flags + k l2norm ----------------
__global__ __launch_bounds__(256) void kv_kernel(const float* __restrict__ text,
                                                 const float* __restrict__ Wk, const float* __restrict__ bk,
                                                 const float* __restrict__ Wv, const float* __restrict__ bv) {
    int bt = blockIdx.x;          // b*NT + t
    int c  = threadIdx.x;         // output channel
    __shared__ float txt[CTD];
    __shared__ float red[256];
    const float* trow = text + (size_t)bt * CTD;
    txt[c] = trow[c]; txt[c+256] = trow[c+256];
    __syncthreads();
    red[c] = fabsf(txt[c]) + fabsf(txt[c+256]);
    __syncthreads();
    for (int s = 128; s; s >>= 1) { if (c < s) red[c] += red[c+s]; __syncthreads(); }
    if (c == 0) g_pad[bt] = (red[0] <= 1e-6f);
    float kc = bk[c], vc = bv[c];
    for (int kk = 0; kk < CTD; kk++) {
        float t = txt[kk];
        kc += t * Wk[kk*CVD + c];
        vc += t * Wv[kk*CVD + c];
    }
    float ss = kc * kc;
#pragma unroll
    for (int o = 16; o; o >>= 1) ss += __shfl_xor_sync(~0u, ss, o);
    kc /= fmaxf(sqrtf(ss), 1e-6f);
    g_k[(size_t)bt*CVD + c] = kc;
    g_v[(size_t)bt*CVD + c] = vc;
}

// ---------------- attention: block per (b,n), warp per head ----------------
__global__ __launch_bounds__(256) void attn_kernel(const float* __restrict__ logit_scale) {
    int row = blockIdx.x;
    int b   = row >> 12;
    int tid = threadIdx.x;
    int h = tid >> 5, lane = tid & 31;
    __shared__ float qs[CVD];
    __shared__ int   spad[NT];
    qs[tid] = g_q[(size_t)row * CVD + tid];
    if (tid < NT) spad[tid] = g_pad[b*NT + tid];
    __syncthreads();

    float ls = logit_scale[0];
    float scale = expf(fminf(fmaxf(ls, -2.f), 2.f)) * 0.17677669529663687f;

    const float* kb = g_k + (size_t)b * NT * CVD + h * DH;
    float s[3];
#pragma unroll
    for (int i = 0; i < 3; i++) {
        int t = lane + 32*i;
        float sv = -INFINITY;
        if (t < NT && !spad[t]) {
            const float* kr = kb + (size_t)t * CVD;
            float acc = 0.f;
#pragma unroll
            for (int d = 0; d < DH; d++) acc += qs[h*DH + d] * kr[d];
            sv = acc * scale;
        }
        s[i] = sv;
    }

    float topv[TOPM]; int topt[TOPM];
#pragma unroll
    for (int it = 0; it < TOPM; it++) {
        float bv = s[0]; int bt = lane;
        if (lane + 32 < NT && s[1] > bv) { bv = s[1]; bt = lane + 32; }
        if (lane + 64 < NT && s[2] > bv) { bv = s[2]; bt = lane + 64; }
#pragma unroll
        for (int o = 16; o; o >>= 1) {
            float ov = __shfl_xor_sync(~0u, bv, o);
            int   ot = __shfl_xor_sync(~0u, bt, o);
            if (ov > bv || (ov == bv && ot < bt)) { bv = ov; bt = ot; }
        }
        topv[it] = bv; topt[it] = bt;
        if ((bt & 31) == lane) s[bt >> 5] = -INFINITY;
    }

    float outv = 0.f;
    float m = topv[0];
    if (!(m == -INFINITY)) {
        float e[TOPM]; float ws = 0.f;
#pragma unroll
        for (int i = 0; i < TOPM; i++) { e[i] = expf(topv[i] - m); ws += e[i]; }
        float inv = 1.f / ws;
        const float* vb = g_v + (size_t)b * NT * CVD + h * DH + lane;
#pragma unroll
        for (int i = 0; i < TOPM; i++) outv += (e[i] * inv) * vb[(size_t)topt[i] * CVD];
    }
    g_aligned[(size_t)row * CVD + h*DH + lane] = outv;
}

// ---------------- TF32 helpers ----------------
__device__ __forceinline__ void tf32_split(float x, uint32_t& hi, uint32_t& lo) {
    float h; asm("cvt.rna.tf32.f32 %0, %1;" : "=f"(h) : "f"(x));
    float l = x - h;
    float l2; asm("cvt.rna.tf32.f32 %0, %1;" : "=f"(l2) : "f"(l));
    hi = __float_as_uint(h); lo = __float_as_uint(l2);
}

__device__ __forceinline__ void mma8(float* c, const uint32_t* a, const uint32_t* b) {
    asm volatile("mma.sync.aligned.m16n8k8.row.col.f32.tf32.tf32.f32 "
        "{%0,%1,%2,%3}, {%4,%5,%6,%7}, {%8,%9}, {%0,%1,%2,%3};"
        : "+f"(c[0]), "+f"(c[1]), "+f"(c[2]), "+f"(c[3])
        : "r"(a[0]), "r"(a[1]), "r"(a[2]), "r"(a[3]), "r"(b[0]), "r"(b[1]));
}

// ---------------- 3xTF32 tensor-core GEMM: C = A(MxK)@B(KxN) + bias ----------------
// mode: 0 = plain, 1 = exact gelu, 2 = per-32-col l2norm (q heads). res: optional +residual.
// Block tile 128x64, BK=32, 8 warps (4 along M x 2 along N), warp tile 32x32 = 2x4 m16n8 tiles.
__global__ __launch_bounds__(256) void gemm_tf32_kernel(const float* __restrict__ A,
                                                        const float* __restrict__ B,
                                                        const float* __restrict__ bias,
                                                        const float* __restrict__ res,
                                                        float* __restrict__ C,
                                                        int M, int N, int K, int mode) {
    __shared__ float Ast[32][136];  // k-major transposed A tile, padded (8k+g banks distinct)
    __shared__ float Bs[32][72];    // k-major B tile, padded   (8k+n banks distinct)

    int tid  = threadIdx.x;
    int lane = tid & 31, wid = tid >> 5;
    int warpM = wid & 3, warpN = wid >> 2;
    int g = lane >> 2, t4 = lane & 3;
    int m0 = blockIdx.y * 128, n0 = blockIdx.x * 64;
    int mbase = warpM * 32, nbase = warpN * 32;

    float c[2][4][4];
#pragma unroll
    for (int i = 0; i < 2; i++)
#pragma unroll
        for (int j = 0; j < 4; j++)
#pragma unroll
            for (int l = 0; l < 4; l++) c[i][j][l] = 0.f;

    // loader coords
    int ar  = tid >> 1;           // A row 0..127
    int ac0 = (tid & 1) * 16;     // A col base (16 each)
    int br  = tid >> 3;           // B row 0..31
    int bc0 = (tid & 7) * 8;      // B col base (8 each)
    const float* Aptr = A + (size_t)(m0 + ar) * K + ac0;
    const float* Bptr = B + (size_t)br * N + n0 + bc0;

    for (int k0 = 0; k0 < K; k0 += 32) {
        float4 av[4];
#pragma unroll
        for (int i = 0; i < 4; i++) av[i] = *(const float4*)(Aptr + k0 + i*4);
        float4 bv0 = *(const float4*)(Bptr + (size_t)k0 * N);
        float4 bv1 = *(const float4*)(Bptr + (size_t)k0 * N + 4);

        __syncthreads();
#pragma unroll
        for (int i = 0; i < 4; i++) {
            Ast[ac0 + i*4 + 0][ar] = av[i].x;
            Ast[ac0 + i*4 + 1][ar] = av[i].y;
            Ast[ac0 + i*4 + 2][ar] = av[i].z;
            Ast[ac0 + i*4 + 3][ar] = av[i].w;
        }
        *(float4*)&Bs[br][bc0]     = bv0;
        *(float4*)&Bs[br][bc0 + 4] = bv1;
        __syncthreads();

#pragma unroll
        for (int ks = 0; ks < 32; ks += 8) {
            uint32_t ah[2][4], al[2][4];
#pragma unroll
            for (int mt = 0; mt < 2; mt++) {
                int r0 = mbase + mt*16 + g;
                float x0 = Ast[ks + t4    ][r0];
                float x1 = Ast[ks + t4    ][r0 + 8];
                float x2 = Ast[ks + t4 + 4][r0];
                float x3 = Ast[ks + t4 + 4][r0 + 8];
                tf32_split(x0, ah[mt][0], al[mt][0]);
                tf32_split(x1, ah[mt][1], al[mt][1]);
                tf32_split(x2, ah[mt][2], al[mt][2]);
                tf32_split(x3, ah[mt][3], al[mt][3]);
            }
            uint32_t bh[4][2], bl[4][2];
#pragma unroll
            for (int nt = 0; nt < 4; nt++) {
                int cn = nbase + nt*8 + g;
                float y0 = Bs[ks + t4    ][cn];
                float y1 = Bs[ks + t4 + 4][cn];
                tf32_split(y0, bh[nt][0], bl[nt][0]);
                tf32_split(y1, bh[nt][1], bl[nt][1]);
            }
#pragma unroll
            for (int mt = 0; mt < 2; mt++)
#pragma unroll
                for (int nt = 0; nt < 4; nt++) {
                    mma8(c[mt][nt], al[mt], bh[nt]);   // small terms first
                    mma8(c[mt][nt], ah[mt], bl[nt]);
                    mma8(c[mt][nt], ah[mt], bh[nt]);
                }
        }
    }

    // epilogue: bias -> (optional l2norm) -> (optional gelu) -> (optional res) -> store
#pragma unroll
    for (int mt = 0; mt < 2; mt++)
#pragma unroll
        for (int nt = 0; nt < 4; nt++) {
            int col = n0 + nbase + nt*8 + t4*2;
            float b0v = bias[col], b1v = bias[col + 1];
            c[mt][nt][0] += b0v; c[mt][nt][1] += b1v;
            c[mt][nt][2] += b0v; c[mt][nt][3] += b1v;
        }

    if (mode == 2) {
        // l2 norm across this warp's 32 cols (= one head) per row
#pragma unroll
        for (int mt = 0; mt < 2; mt++) {
            float ss0 = 0.f, ss1 = 0.f;
#pragma unroll
            for (int nt = 0; nt < 4; nt++) {
                ss0 += c[mt][nt][0]*c[mt][nt][0] + c[mt][nt][1]*c[mt][nt][1];
                ss1 += c[mt][nt][2]*c[mt][nt][2] + c[mt][nt][3]*c[mt][nt][3];
            }
            ss0 += __shfl_xor_sync(~0u, ss0, 1); ss0 += __shfl_xor_sync(~0u, ss0, 2);
            ss1 += __shfl_xor_sync(~0u, ss1, 1); ss1 += __shfl_xor_sync(~0u, ss1, 2);
            float i0 = 1.f / fmaxf(sqrtf(ss0), 1e-6f);
            float i1 = 1.f / fmaxf(sqrtf(ss1), 1e-6f);
#pragma unroll
            for (int nt = 0; nt < 4; nt++) {
                c[mt][nt][0] *= i0; c[mt][nt][1] *= i0;
                c[mt][nt][2] *= i1; c[mt][nt][3] *= i1;
            }
        }
    }

#pragma unroll
    for (int mt = 0; mt < 2; mt++)
#pragma unroll
        for (int nt = 0; nt < 4; nt++) {
            int col = n0 + nbase + nt*8 + t4*2;
            size_t r0 = (size_t)(m0 + mbase + mt*16 + g);
            size_t r1 = r0 + 8;
            float v0 = c[mt][nt][0], v1 = c[mt][nt][1];
            float v2 = c[mt][nt][2], v3 = c[mt][nt][3];
            if (mode == 1) {
                v0 = 0.5f*v0*(1.f + erff(v0*0.70710678118654752f));
                v1 = 0.5f*v1*(1.f + erff(v1*0.70710678118654752f));
                v2 = 0.5f*v2*(1.f + erff(v2*0.70710678118654752f));
                v3 = 0.5f*v3*(1.f + erff(v3*0.70710678118654752f));
            }
            if (res) {
                v0 += res[r0*N + col]; v1 += res[r0*N + col + 1];
                v2 += res[r1*N + col]; v3 += res[r1*N + col + 1];
            }
            *(float2*)&C[r0*N + col] = make_float2(v0, v1);
            *(float2*)&C[r1*N + col] = make_float2(v2, v3);
        }
}

// ---------------- launch ----------------
extern "C" void kernel_launch(void* const* d_in, const int* in_sizes, int n_in,
                              void* d_out, int out_size) {
    const float* vis   = (const float*)d_in[0];
    const float* text  = (const float*)d_in[1];
    const float* Wq    = (const float*)d_in[2];
    const float* bq    = (const float*)d_in[3];
    const float* Wk    = (const float*)d_in[4];
    const float* bk    = (const float*)d_in[5];
    const float* Wv    = (const float*)d_in[6];
    const float* bv    = (const float*)d_in[7];
    const float* Wo    = (const float*)d_in[8];
    const float* bo    = (const float*)d_in[9];
    const float* g1    = (const float*)d_in[10];
    const float* b1    = (const float*)d_in[11];
    const float* g2    = (const float*)d_in[12];
    const float* b2    = (const float*)d_in[13];
    const float* Wf1   = (const float*)d_in[14];
    const float* bf1   = (const float*)d_in[15];
    const float* Wf2   = (const float*)d_in[16];
    const float* bf2   = (const float*)d_in[17];
    const float* ls    = (const float*)d_in[18];
    const float* alpha = (const float*)d_in[19];
    float* out = (float*)d_out;

    float *px, *pq, *paligned, *pproj, *py2, *phdn;
    cudaGetSymbolAddress((void**)&px,       g_x);
    cudaGetSymbolAddress((void**)&pq,       g_q);
    cudaGetSymbolAddress((void**)&paligned, g_aligned);
    cudaGetSymbolAddress((void**)&pproj,    g_proj);
    cudaGetSymbolAddress((void**)&py2,      g_y2);
    cudaGetSymbolAddress((void**)&phdn,     g_hdn);

    // 1) LN1
    ln1_kernel<<<ROWS/8, 256>>>(vis, g1, b1);
    // 2) K/V projection + pad + k-norm
    kv_kernel<<<NB*NT, 256>>>(text, Wk, bk, Wv, bv);
    // 3) q = l2norm_per_head(x @ Wq + bq)   (norm fused into epilogue)
    gemm_tf32_kernel<<<dim3(CVD/64, ROWS/128), 256>>>(px, Wq, bq, nullptr, pq, ROWS, CVD, CVD, 2);
    // 4) attention
    attn_kernel<<<ROWS, 256>>>(ls);
    // 5) proj = aligned @ Wo + bo
    gemm_tf32_kernel<<<dim3(CVD/64, ROWS/128), 256>>>(paligned, Wo, bo, nullptr, pproj, ROWS, CVD, CVD, 0);
    // 6) y2 = LN2(x + alpha*proj)
    ln2res_kernel<<<ROWS/8, 256>>>(g2, b2, alpha);
    // 7) hdn = gelu(y2 @ Wf1 + bf1)
    gemm_tf32_kernel<<<dim3(4*CVD/64, ROWS/128), 256>>>(py2, Wf1, bf1, nullptr, phdn, ROWS, 4*CVD, CVD, 1);
    // 8) out = y2 + hdn @ Wf2 + bf2
    gemm_tf32_kernel<<<dim3(CVD/64, ROWS/128), 256>>>(phdn, Wf2, bf2, py2, out, ROWS, CVD, 4*CVD, 0);
}

// round 4
// speedup vs baseline: 2.8279x; 2.5714x over previous
#include <cuda_runtime.h>
#include <math.h>
#include <stdint.h>

// ---------------- problem constants ----------------
#define NB   8
#define NN   4096          // H*W
#define CVD  256
#define CTD  512
#define NT   77
#define TPAD 96
#define NHH  8
#define DH   32
#define TOPM 5
#define ROWS (NB*NN)       // 32768

// ---------------- scratch (device globals; no allocs allowed) ----------------
__device__ float g_x[ROWS*CVD];          // LN1 output
__device__ float g_q[ROWS*CVD];          // q projection (l2-normed in epilogue)
__device__ float g_kT[NB*NHH*DH*TPAD];   // k transposed [b][h][d][t], l2-normed; t>=77 stays 0
__device__ float g_v[NB*NT*CVD];         // v
__device__ int   g_pad[NB*NT];           // pad flags
__device__ float g_aligned[ROWS*CVD];    // attention output
__device__ float g_proj[ROWS*CVD];       // aligned @ Wo + bo
__device__ float g_y2[ROWS*CVD];         // LN2 output
__device__ float g_hdn[ROWS*4*CVD];      // FFN hidden (gelu)

// ---------------- LN1 ----------------
__global__ __launch_bounds__(256) void ln1_kernel(const float* __restrict__ in,
                                                  const float* __restrict__ g,
                                                  const float* __restrict__ b) {
    int warp = (blockIdx.x * blockDim.x + threadIdx.x) >> 5;
    int lane = threadIdx.x & 31;
    const float* row = in + (size_t)warp * CVD;
    float v[8]; float s = 0.f, ss = 0.f;
#pragma unroll
    for (int i = 0; i < 8; i++) { v[i] = row[lane*8 + i]; s += v[i]; ss += v[i]*v[i]; }
#pragma unroll
    for (int o = 16; o; o >>= 1) { s += __shfl_xor_sync(~0u, s, o); ss += __shfl_xor_sync(~0u, ss, o); }
    float mu  = s * (1.f/CVD);
    float var = ss * (1.f/CVD) - mu*mu;
    float inv = rsqrtf(var + 1e-5f);
    float* orow = g_x + (size_t)warp * CVD;
#pragma unroll
    for (int i = 0; i < 8; i++) { int c = lane*8 + i; orow[c] = (v[i]-mu)*inv*g[c] + b[c]; }
}

// ---------------- LN2 + residual ----------------
__global__ __launch_bounds__(256) void ln2res_kernel(const float* __restrict__ g,
                                                     const float* __restrict__ b,
                                                     const float* __restrict__ alpha_p) {
    int warp = (blockIdx.x * blockDim.x + threadIdx.x) >> 5;
    int lane = threadIdx.x & 31;
    float alpha = alpha_p[0];
    const float* xr = g_x    + (size_t)warp * CVD;
    const float* pr = g_proj + (size_t)warp * CVD;
    float v[8]; float s = 0.f, ss = 0.f;
#pragma unroll
    for (int i = 0; i < 8; i++) {
        int c = lane*8 + i;
        v[i] = xr[c] + alpha * pr[c];
        s += v[i]; ss += v[i]*v[i];
    }
#pragma unroll
    for (int o = 16; o; o >>= 1) { s += __shfl_xor_sync(~0u, s, o); ss += __shfl_xor_sync(~0u, ss, o); }
    float mu  = s * (1.f/CVD);
    float var = ss * (1.f/CVD) - mu*mu;
    float inv = rsqrtf(var + 1e-5f);
    float* orow = g_y2 + (size_t)warp * CVD;
#pragma unroll
    for (int i = 0; i < 8; i++) { int c = lane*8 + i; orow[c] = (v[i]-mu)*inv*g[c] + b[c]; }
}

// ---------------- K/V projection + pad flags + k l2norm + K transpose ----------------
__global__ __launch_bounds__(256) void kv_kernel(const float* __restrict__ text,
                                                 const float* __restrict__ Wk, const float* __restrict__ bk,
                                                 const float* __restrict__ Wv, const float* __restrict__ bv) {
    int bt = blockIdx.x;          // b*NT + t
    int b  = bt / NT, t = bt - b * NT;
    int c  = threadIdx.x;         // output channel
    __shared__ float txt[CTD];
    __shared__ float red[256];
    const float* trow = text + (size_t)bt * CTD;
    txt[c] = trow[c]; txt[c+256] = trow[c+256];
    __syncthreads();
    red[c] = fabsf(txt[c]) + fabsf(txt[c+256]);
    __syncthreads();
    for (int s = 128; s; s >>= 1) { if (c < s) red[c] += red[c+s]; __syncthreads(); }
    if (c == 0) g_pad[bt] = (red[0] <= 1e-6f);
    float kc = bk[c], vc = bv[c];
#pragma unroll 4
    for (int kk = 0; kk < CTD; kk++) {
        float tv = txt[kk];
        kc += tv * Wk[kk*CVD + c];
        vc += tv * Wv[kk*CVD + c];
    }
    float ss = kc * kc;
#pragma unroll
    for (int o = 16; o; o >>= 1) ss += __shfl_xor_sync(~0u, ss, o);
    kc /= fmaxf(sqrtf(ss), 1e-6f);
    int h = c >> 5, d = c & 31;
    g_kT[((b*NHH + h)*DH + d)*TPAD + t] = kc;       // transposed store
    g_v[(size_t)bt*CVD + c] = vc;
}

// ---------------- attention: block per (b,n), warp per head, K read t-coalesced ----------------
__global__ __launch_bounds__(256) void attn_kernel(const float* __restrict__ logit_scale) {
    int row = blockIdx.x;
    int b   = row >> 12;
    int tid = threadIdx.x;
    int h = tid >> 5, lane = tid & 31;
    __shared__ float qs[CVD];
    __shared__ int   spad[NT];
    qs[tid] = g_q[(size_t)row * CVD + tid];
    if (tid < NT) spad[tid] = g_pad[b*NT + tid];
    __syncthreads();

    float ls = logit_scale[0];
    float scale = expf(fminf(fmaxf(ls, -2.f), 2.f)) * 0.17677669529663687f;

    const float* kT = g_kT + ((size_t)(b*NHH + h) * DH) * TPAD;  // [d][t]
    float a0 = 0.f, a1 = 0.f, a2 = 0.f;
#pragma unroll
    for (int d = 0; d < DH; d++) {
        float qd = qs[h*DH + d];
        const float* kr = kT + d*TPAD;
        a0 += qd * kr[lane];
        a1 += qd * kr[lane + 32];
        a2 += qd * kr[lane + 64];       // t>=77 slots are 0 -> masked below
    }

    float s[3];
    s[0] = !spad[lane] ? a0 * scale : -INFINITY;
    s[1] = (lane + 32 < NT && !spad[lane + 32]) ? a1 * scale : -INFINITY;
    s[2] = (lane + 64 < NT && !spad[lane + 64]) ? a2 * scale : -INFINITY;

    float topv[TOPM]; int topt[TOPM];
#pragma unroll
    for (int it = 0; it < TOPM; it++) {
        float bv = s[0]; int bt = lane;
        if (s[1] > bv) { bv = s[1]; bt = lane + 32; }
        if (s[2] > bv) { bv = s[2]; bt = lane + 64; }
#pragma unroll
        for (int o = 16; o; o >>= 1) {
            float ov = __shfl_xor_sync(~0u, bv, o);
            int   ot = __shfl_xor_sync(~0u, bt, o);
            if (ov > bv || (ov == bv && ot < bt)) { bv = ov; bt = ot; }
        }
        topv[it] = bv; topt[it] = bt;
        if ((bt & 31) == lane) s[bt >> 5] = -INFINITY;
    }

    float outv = 0.f;
    float m = topv[0];
    if (!(m == -INFINITY)) {
        float e[TOPM]; float ws = 0.f;
#pragma unroll
        for (int i = 0; i < TOPM; i++) { e[i] = expf(topv[i] - m); ws += e[i]; }
        float inv = 1.f / ws;
        const float* vb = g_v + (size_t)b * NT * CVD + h * DH + lane;
#pragma unroll
        for (int i = 0; i < TOPM; i++) outv += (e[i] * inv) * vb[(size_t)topt[i] * CVD];
    }
    g_aligned[(size_t)row * CVD + h*DH + lane] = outv;
}

// ---------------- TF32 helpers ----------------
__device__ __forceinline__ void tf32_split(float x, float& hi, float& lo) {
    float h; asm("cvt.rna.tf32.f32 %0, %1;" : "=f"(h) : "f"(x));
    float l = x - h;
    asm("cvt.rna.tf32.f32 %0, %1;" : "=f"(lo) : "f"(l));
    hi = h;
}
__device__ __forceinline__ void mma8(float* c, const uint32_t* a, const uint32_t* b) {
    asm volatile("mma.sync.aligned.m16n8k8.row.col.f32.tf32.tf32.f32 "
        "{%0,%1,%2,%3}, {%4,%5,%6,%7}, {%8,%9}, {%0,%1,%2,%3};"
        : "+f"(c[0]), "+f"(c[1]), "+f"(c[2]), "+f"(c[3])
        : "r"(a[0]), "r"(a[1]), "r"(a[2]), "r"(a[3]), "r"(b[0]), "r"(b[1]));
}

// ---------------- 3xTF32 tensor-core GEMM (split at staging): C = A@B + bias ----------------
// mode: 0 plain, 1 exact gelu, 2 per-32-col l2norm. res: optional +residual.
// Block 128x64, BK=16, 8 warps (4M x 2N), warp 32x32 = 2x4 m16n8k8.
__global__ __launch_bounds__(256) void gemm_tf32_kernel(const float* __restrict__ A,
                                                        const float* __restrict__ B,
                                                        const float* __restrict__ bias,
                                                        const float* __restrict__ res,
                                                        float* __restrict__ C,
                                                        int M, int N, int K, int mode) {
    __shared__ float Ah[16][136], Al[16][136];   // k-major transposed A hi/lo (stride 136 = 8 mod 32)
    __shared__ float Bh[16][72],  Bl[16][72];    // k-major B hi/lo (stride 72 = 8 mod 32)

    int tid  = threadIdx.x;
    int lane = tid & 31, wid = tid >> 5;
    int warpM = wid & 3, warpN = wid >> 2;
    int g = lane >> 2, t4 = lane & 3;
    int m0 = blockIdx.y * 128, n0 = blockIdx.x * 64;
    int mbase = warpM * 32, nbase = warpN * 32;

    float c[2][4][4];
#pragma unroll
    for (int i = 0; i < 2; i++)
#pragma unroll
        for (int j = 0; j < 4; j++)
#pragma unroll
            for (int l = 0; l < 4; l++) c[i][j][l] = 0.f;

    // loaders: A tile 128x16 (8/thread), B tile 16x64 (4/thread)
    int ar  = tid >> 1;
    int ac0 = (tid & 1) * 8;
    int br  = tid >> 4;
    int bc0 = (tid & 15) * 4;
    const float* Aptr = A + (size_t)(m0 + ar) * K + ac0;
    const float* Bptr = B + (size_t)br * N + n0 + bc0;

    float4 av0 = *(const float4*)(Aptr);
    float4 av1 = *(const float4*)(Aptr + 4);
    float4 bv  = *(const float4*)(Bptr);

    for (int k0 = 0; k0 < K; k0 += 16) {
        // stage current tile, splitting fp32 -> tf32 hi/lo
        float xh, xl;
        tf32_split(av0.x, xh, xl); Ah[ac0+0][ar] = xh; Al[ac0+0][ar] = xl;
        tf32_split(av0.y, xh, xl); Ah[ac0+1][ar] = xh; Al[ac0+1][ar] = xl;
        tf32_split(av0.z, xh, xl); Ah[ac0+2][ar] = xh; Al[ac0+2][ar] = xl;
        tf32_split(av0.w, xh, xl); Ah[ac0+3][ar] = xh; Al[ac0+3][ar] = xl;
        tf32_split(av1.x, xh, xl); Ah[ac0+4][ar] = xh; Al[ac0+4][ar] = xl;
        tf32_split(av1.y, xh, xl); Ah[ac0+5][ar] = xh; Al[ac0+5][ar] = xl;
        tf32_split(av1.z, xh, xl); Ah[ac0+6][ar] = xh; Al[ac0+6][ar] = xl;
        tf32_split(av1.w, xh, xl); Ah[ac0+7][ar] = xh; Al[ac0+7][ar] = xl;
        tf32_split(bv.x, xh, xl); Bh[br][bc0+0] = xh; Bl[br][bc0+0] = xl;
        tf32_split(bv.y, xh, xl); Bh[br][bc0+1] = xh; Bl[br][bc0+1] = xl;
        tf32_split(bv.z, xh, xl); Bh[br][bc0+2] = xh; Bl[br][bc0+2] = xl;
        tf32_split(bv.w, xh, xl); Bh[br][bc0+3] = xh; Bl[br][bc0+3] = xl;
        __syncthreads();

        // prefetch next tile
        if (k0 + 16 < K) {
            av0 = *(const float4*)(Aptr + k0 + 16);
            av1 = *(const float4*)(Aptr + k0 + 20);
            bv  = *(const float4*)(Bptr + (size_t)(k0 + 16) * N);
        }

#pragma unroll
        for (int ks = 0; ks < 16; ks += 8) {
            uint32_t ah[2][4], al[2][4], bh[4][2], bl[4][2];
#pragma unroll
            for (int mt = 0; mt < 2; mt++) {
                int r0 = mbase + mt*16 + g;
                ah[mt][0] = __float_as_uint(Ah[ks + t4    ][r0]);
                ah[mt][1] = __float_as_uint(Ah[ks + t4    ][r0 + 8]);
                ah[mt][2] = __float_as_uint(Ah[ks + t4 + 4][r0]);
                ah[mt][3] = __float_as_uint(Ah[ks + t4 + 4][r0 + 8]);
                al[mt][0] = __float_as_uint(Al[ks + t4    ][r0]);
                al[mt][1] = __float_as_uint(Al[ks + t4    ][r0 + 8]);
                al[mt][2] = __float_as_uint(Al[ks + t4 + 4][r0]);
                al[mt][3] = __float_as_uint(Al[ks + t4 + 4][r0 + 8]);
            }
#pragma unroll
            for (int nt = 0; nt < 4; nt++) {
                int cn = nbase + nt*8 + g;
                bh[nt][0] = __float_as_uint(Bh[ks + t4    ][cn]);
                bh[nt][1] = __float_as_uint(Bh[ks + t4 + 4][cn]);
                bl[nt][0] = __float_as_uint(Bl[ks + t4    ][cn]);
                bl[nt][1] = __float_as_uint(Bl[ks + t4 + 4][cn]);
            }
#pragma unroll
            for (int mt = 0; mt < 2; mt++)
#pragma unroll
                for (int nt = 0; nt < 4; nt++) {
                    mma8(c[mt][nt], al[mt], bh[nt]);   // small terms first
                    mma8(c[mt][nt], ah[mt], bl[nt]);
                    mma8(c[mt][nt], ah[mt], bh[nt]);
                }
        }
        __syncthreads();
    }

    // epilogue: bias -> (optional l2norm) -> (optional gelu) -> (optional res) -> store
#pragma unroll
    for (int mt = 0; mt < 2; mt++)
#pragma unroll
        for (int nt = 0; nt < 4; nt++) {
            int col = n0 + nbase + nt*8 + t4*2;
            float b0v = bias[col], b1v = bias[col + 1];
            c[mt][nt][0] += b0v; c[mt][nt][1] += b1v;
            c[mt][nt][2] += b0v; c[mt][nt][3] += b1v;
        }

    if (mode == 2) {
#pragma unroll
        for (int mt = 0; mt < 2; mt++) {
            float ss0 = 0.f, ss1 = 0.f;
#pragma unroll
            for (int nt = 0; nt < 4; nt++) {
                ss0 += c[mt][nt][0]*c[mt][nt][0] + c[mt][nt][1]*c[mt][nt][1];
                ss1 += c[mt][nt][2]*c[mt][nt][2] + c[mt][nt][3]*c[mt][nt][3];
            }
            ss0 += __shfl_xor_sync(~0u, ss0, 1); ss0 += __shfl_xor_sync(~0u, ss0, 2);
            ss1 += __shfl_xor_sync(~0u, ss1, 1); ss1 += __shfl_xor_sync(~0u, ss1, 2);
            float i0 = 1.f / fmaxf(sqrtf(ss0), 1e-6f);
            float i1 = 1.f / fmaxf(sqrtf(ss1), 1e-6f);
#pragma unroll
            for (int nt = 0; nt < 4; nt++) {
                c[mt][nt][0] *= i0; c[mt][nt][1] *= i0;
                c[mt][nt][2] *= i1; c[mt][nt][3] *= i1;
            }
        }
    }

#pragma unroll
    for (int mt = 0; mt < 2; mt++)
#pragma unroll
        for (int nt = 0; nt < 4; nt++) {
            int col = n0 + nbase + nt*8 + t4*2;
            size_t r0 = (size_t)(m0 + mbase + mt*16 + g);
            size_t r1 = r0 + 8;
            float v0 = c[mt][nt][0], v1 = c[mt][nt][1];
            float v2 = c[mt][nt][2], v3 = c[mt][nt][3];
            if (mode == 1) {
                v0 = 0.5f*v0*(1.f + erff(v0*0.70710678118654752f));
                v1 = 0.5f*v1*(1.f + erff(v1*0.70710678118654752f));
                v2 = 0.5f*v2*(1.f + erff(v2*0.70710678118654752f));
                v3 = 0.5f*v3*(1.f + erff(v3*0.70710678118654752f));
            }
            if (res) {
                v0 += res[r0*N + col]; v1 += res[r0*N + col + 1];
                v2 += res[r1*N + col]; v3 += res[r1*N + col + 1];
            }
            *(float2*)&C[r0*N + col] = make_float2(v0, v1);
            *(float2*)&C[r1*N + col] = make_float2(v2, v3);
        }
}

// ---------------- launch ----------------
extern "C" void kernel_launch(void* const* d_in, const int* in_sizes, int n_in,
                              void* d_out, int out_size) {
    const float* vis   = (const float*)d_in[0];
    const float* text  = (const float*)d_in[1];
    const float* Wq    = (const float*)d_in[2];
    const float* bq    = (const float*)d_in[3];
    const float* Wk    = (const float*)d_in[4];
    const float* bk    = (const float*)d_in[5];
    const float* Wv    = (const float*)d_in[6];
    const float* bv    = (const float*)d_in[7];
    const float* Wo    = (const float*)d_in[8];
    const float* bo    = (const float*)d_in[9];
    const float* g1    = (const float*)d_in[10];
    const float* b1    = (const float*)d_in[11];
    const float* g2    = (const float*)d_in[12];
    const float* b2    = (const float*)d_in[13];
    const float* Wf1   = (const float*)d_in[14];
    const float* bf1   = (const float*)d_in[15];
    const float* Wf2   = (const float*)d_in[16];
    const float* bf2   = (const float*)d_in[17];
    const float* ls    = (const float*)d_in[18];
    const float* alpha = (const float*)d_in[19];
    float* out = (float*)d_out;

    float *px, *pq, *paligned, *pproj, *py2, *phdn;
    cudaGetSymbolAddress((void**)&px,       g_x);
    cudaGetSymbolAddress((void**)&pq,       g_q);
    cudaGetSymbolAddress((void**)&paligned, g_aligned);
    cudaGetSymbolAddress((void**)&pproj,    g_proj);
    cudaGetSymbolAddress((void**)&py2,      g_y2);
    cudaGetSymbolAddress((void**)&phdn,     g_hdn);

    ln1_kernel<<<ROWS/8, 256>>>(vis, g1, b1);
    kv_kernel<<<NB*NT, 256>>>(text, Wk, bk, Wv, bv);
    gemm_tf32_kernel<<<dim3(CVD/64, ROWS/128), 256>>>(px, Wq, bq, nullptr, pq, ROWS, CVD, CVD, 2);
    attn_kernel<<<ROWS, 256>>>(ls);
    gemm_tf32_kernel<<<dim3(CVD/64, ROWS/128), 256>>>(paligned, Wo, bo, nullptr, pproj, ROWS, CVD, CVD, 0);
    ln2res_kernel<<<ROWS/8, 256>>>(g2, b2, alpha);
    gemm_tf32_kernel<<<dim3(4*CVD/64, ROWS/128), 256>>>(py2, Wf1, bf1, nullptr, phdn, ROWS, 4*CVD, CVD, 1);
    gemm_tf32_kernel<<<dim3(CVD/64, ROWS/128), 256>>>(phdn, Wf2, bf2, py2, out, ROWS, CVD, 4*CVD, 0);
}

// round 5
// speedup vs baseline: 3.7554x; 1.3280x over previous
#include <cuda_runtime.h>
#include <cuda_bf16.h>
#include <math.h>
#include <stdint.h>

// ---------------- problem constants ----------------
#define NB   8
#define NN   4096          // H*W
#define CVD  256
#define CTD  512
#define NT   77
#define TPAD 96
#define NHH  8
#define DH   32
#define TOPM 5
#define ROWS (NB*NN)       // 32768

// ---------------- scratch (device globals; no allocs allowed) ----------------
__device__ float g_x[ROWS*CVD];          // LN1 output
__device__ float g_q[ROWS*CVD];          // q projection (l2-normed in epilogue)
__device__ float g_kT[NB*NHH*DH*TPAD];   // k transposed [b][h][d][t], l2-normed; t>=77 stays 0
__device__ float g_v[NB*NT*CVD];         // v
__device__ int   g_pad[NB*NT];           // pad flags
__device__ float g_aligned[ROWS*CVD];    // attention output
__device__ float g_proj[ROWS*CVD];       // aligned @ Wo + bo
__device__ float g_y2[ROWS*CVD];         // LN2 output
__device__ float g_hdn[ROWS*4*CVD];      // FFN hidden (gelu)

// ---------------- LN1 ----------------
__global__ __launch_bounds__(256) void ln1_kernel(const float* __restrict__ in,
                                                  const float* __restrict__ g,
                                                  const float* __restrict__ b) {
    int warp = (blockIdx.x * blockDim.x + threadIdx.x) >> 5;
    int lane = threadIdx.x & 31;
    const float* row = in + (size_t)warp * CVD;
    float v[8]; float s = 0.f, ss = 0.f;
#pragma unroll
    for (int i = 0; i < 8; i++) { v[i] = row[lane*8 + i]; s += v[i]; ss += v[i]*v[i]; }
#pragma unroll
    for (int o = 16; o; o >>= 1) { s += __shfl_xor_sync(~0u, s, o); ss += __shfl_xor_sync(~0u, ss, o); }
    float mu  = s * (1.f/CVD);
    float var = ss * (1.f/CVD) - mu*mu;
    float inv = rsqrtf(var + 1e-5f);
    float* orow = g_x + (size_t)warp * CVD;
#pragma unroll
    for (int i = 0; i < 8; i++) { int c = lane*8 + i; orow[c] = (v[i]-mu)*inv*g[c] + b[c]; }
}

// ---------------- LN2 + residual ----------------
__global__ __launch_bounds__(256) void ln2res_kernel(const float* __restrict__ g,
                                                     const float* __restrict__ b,
                                                     const float* __restrict__ alpha_p) {
    int warp = (blockIdx.x * blockDim.x + threadIdx.x) >> 5;
    int lane = threadIdx.x & 31;
    float alpha = alpha_p[0];
    const float* xr = g_x    + (size_t)warp * CVD;
    const float* pr = g_proj + (size_t)warp * CVD;
    float v[8]; float s = 0.f, ss = 0.f;
#pragma unroll
    for (int i = 0; i < 8; i++) {
        int c = lane*8 + i;
        v[i] = xr[c] + alpha * pr[c];
        s += v[i]; ss += v[i]*v[i];
    }
#pragma unroll
    for (int o = 16; o; o >>= 1) { s += __shfl_xor_sync(~0u, s, o); ss += __shfl_xor_sync(~0u, ss, o); }
    float mu  = s * (1.f/CVD);
    float var = ss * (1.f/CVD) - mu*mu;
    float inv = rsqrtf(var + 1e-5f);
    float* orow = g_y2 + (size_t)warp * CVD;
#pragma unroll
    for (int i = 0; i < 8; i++) { int c = lane*8 + i; orow[c] = (v[i]-mu)*inv*g[c] + b[c]; }
}

// ---------------- K/V projection + pad flags + k l2norm + K transpose ----------------
__global__ __launch_bounds__(256) void kv_kernel(const float* __restrict__ text,
                                                 const float* __restrict__ Wk, const float* __restrict__ bk,
                                                 const float* __restrict__ Wv, const float* __restrict__ bv) {
    int bt = blockIdx.x;          // b*NT + t
    int b  = bt / NT, t = bt - b * NT;
    int c  = threadIdx.x;         // output channel
    __shared__ float txt[CTD];
    __shared__ float red[256];
    const float* trow = text + (size_t)bt * CTD;
    txt[c] = trow[c]; txt[c+256] = trow[c+256];
    __syncthreads();
    red[c] = fabsf(txt[c]) + fabsf(txt[c+256]);
    __syncthreads();
    for (int s = 128; s; s >>= 1) { if (c < s) red[c] += red[c+s]; __syncthreads(); }
    if (c == 0) g_pad[bt] = (red[0] <= 1e-6f);
    float kc = bk[c], vc = bv[c];
#pragma unroll 4
    for (int kk = 0; kk < CTD; kk++) {
        float tv = txt[kk];
        kc += tv * Wk[kk*CVD + c];
        vc += tv * Wv[kk*CVD + c];
    }
    float ss = kc * kc;
#pragma unroll
    for (int o = 16; o; o >>= 1) ss += __shfl_xor_sync(~0u, ss, o);
    kc /= fmaxf(sqrtf(ss), 1e-6f);
    int h = c >> 5, d = c & 31;
    g_kT[((b*NHH + h)*DH + d)*TPAD + t] = kc;       // transposed store
    g_v[(size_t)bt*CVD + c] = vc;
}

// ---------------- attention: block per (b,n), warp per head, K read t-coalesced ----------------
__global__ __launch_bounds__(256) void attn_kernel(const float* __restrict__ logit_scale) {
    int row = blockIdx.x;
    int b   = row >> 12;
    int tid = threadIdx.x;
    int h = tid >> 5, lane = tid & 31;
    __shared__ float qs[CVD];
    __shared__ int   spad[NT];
    qs[tid] = g_q[(size_t)row * CVD + tid];
    if (tid < NT) spad[tid] = g_pad[b*NT + tid];
    __syncthreads();

    float ls = logit_scale[0];
    float scale = expf(fminf(fmaxf(ls, -2.f), 2.f)) * 0.17677669529663687f;

    const float* kT = g_kT + ((size_t)(b*NHH + h) * DH) * TPAD;  // [d][t]
    float a0 = 0.f, a1 = 0.f, a2 = 0.f;
#pragma unroll
    for (int d = 0; d < DH; d++) {
        float qd = qs[h*DH + d];
        const float* kr = kT + d*TPAD;
        a0 += qd * kr[lane];
        a1 += qd * kr[lane + 32];
        a2 += qd * kr[lane + 64];
    }

    float s[3];
    s[0] = !spad[lane] ? a0 * scale : -INFINITY;
    s[1] = (lane + 32 < NT && !spad[lane + 32]) ? a1 * scale : -INFINITY;
    s[2] = (lane + 64 < NT && !spad[lane + 64]) ? a2 * scale : -INFINITY;

    float topv[TOPM]; int topt[TOPM];
#pragma unroll
    for (int it = 0; it < TOPM; it++) {
        float bv = s[0]; int bt = lane;
        if (s[1] > bv) { bv = s[1]; bt = lane + 32; }
        if (s[2] > bv) { bv = s[2]; bt = lane + 64; }
#pragma unroll
        for (int o = 16; o; o >>= 1) {
            float ov = __shfl_xor_sync(~0u, bv, o);
            int   ot = __shfl_xor_sync(~0u, bt, o);
            if (ov > bv || (ov == bv && ot < bt)) { bv = ov; bt = ot; }
        }
        topv[it] = bv; topt[it] = bt;
        if ((bt & 31) == lane) s[bt >> 5] = -INFINITY;
    }

    float outv = 0.f;
    float m = topv[0];
    if (!(m == -INFINITY)) {
        float e[TOPM]; float ws = 0.f;
#pragma unroll
        for (int i = 0; i < TOPM; i++) { e[i] = expf(topv[i] - m); ws += e[i]; }
        float inv = 1.f / ws;
        const float* vb = g_v + (size_t)b * NT * CVD + h * DH + lane;
#pragma unroll
        for (int i = 0; i < TOPM; i++) outv += (e[i] * inv) * vb[(size_t)topt[i] * CVD];
    }
    g_aligned[(size_t)row * CVD + h*DH + lane] = outv;
}

// ---------------- bf16 split helpers ----------------
__device__ __forceinline__ void bf16_split_pack(float x0, float x1, uint32_t& hi, uint32_t& lo) {
    __nv_bfloat16 h0 = __float2bfloat16_rn(x0);
    __nv_bfloat16 h1 = __float2bfloat16_rn(x1);
    __nv_bfloat16 l0 = __float2bfloat16_rn(x0 - __bfloat162float(h0));
    __nv_bfloat16 l1 = __float2bfloat16_rn(x1 - __bfloat162float(h1));
    hi = (uint32_t)__bfloat16_as_ushort(h0) | ((uint32_t)__bfloat16_as_ushort(h1) << 16);
    lo = (uint32_t)__bfloat16_as_ushort(l0) | ((uint32_t)__bfloat16_as_ushort(l1) << 16);
}
__device__ __forceinline__ void mma16(float* c, const uint32_t* a, const uint32_t* b) {
    asm volatile("mma.sync.aligned.m16n8k16.row.col.f32.bf16.bf16.f32 "
        "{%0,%1,%2,%3}, {%4,%5,%6,%7}, {%8,%9}, {%0,%1,%2,%3};"
        : "+f"(c[0]), "+f"(c[1]), "+f"(c[2]), "+f"(c[3])
        : "r"(a[0]), "r"(a[1]), "r"(a[2]), "r"(a[3]), "r"(b[0]), "r"(b[1]));
}

// ---------------- split-bf16 tensor-core GEMM (3x m16n8k16): C = A@B + bias ----------------
// mode: 0 plain, 1 exact gelu, 2 per-32-col l2norm. res: optional +residual.
// Block 128x64, BK=16, 8 warps (4M x 2N), warp 32x32 = 2x4 tiles. 2-stage smem double buffer.
// Smem tiles hold bf16x2 k-pairs as uint32: Apair[k2][m] (stride 136), Bpair[k2][n] (stride 72).
__global__ __launch_bounds__(256) void gemm_bf16s_kernel(const float* __restrict__ A,
                                                         const float* __restrict__ B,
                                                         const float* __restrict__ bias,
                                                         const float* __restrict__ res,
                                                         float* __restrict__ C,
                                                         int M, int N, int K, int mode) {
    __shared__ uint32_t Ah[2][8][136], Al[2][8][136];  // stride 136 = 8 mod 32 -> conflict-free
    __shared__ uint32_t Bh[2][8][72],  Bl[2][8][72];

    int tid  = threadIdx.x;
    int lane = tid & 31, wid = tid >> 5;
    int warpM = wid & 3, warpN = wid >> 2;
    int g = lane >> 2, t4 = lane & 3;
    int m0 = blockIdx.y * 128, n0 = blockIdx.x * 64;
    int mbase = warpM * 32, nbase = warpN * 32;

    float c[2][4][4];
#pragma unroll
    for (int i = 0; i < 2; i++)
#pragma unroll
        for (int j = 0; j < 4; j++)
#pragma unroll
            for (int l = 0; l < 4; l++) c[i][j][l] = 0.f;

    // A loader: 128 rows x 16 k / 256 thr -> 8 floats each (2x float4)
    int ar   = tid >> 1;
    int ac0  = (tid & 1) * 8;       // k offset 0 or 8
    int k2a  = ac0 >> 1;            // pair row base (0 or 4)
    // B loader: 8 k2-rows x 64 cols -> 2 pairs each (4 floats from 4 k-rows, 1 col... see below)
    int bn   = tid & 63;            // col
    int k2b  = (tid >> 6) * 2;      // pair rows k2b, k2b+1
    const float* Aptr = A + (size_t)(m0 + ar) * K + ac0;
    const float* Bptr = B + (size_t)(2*k2b) * N + n0 + bn;

    float4 av0, av1;
    float  b00, b01, b10, b11;
    av0 = *(const float4*)(Aptr);
    av1 = *(const float4*)(Aptr + 4);
    b00 = Bptr[0]; b01 = Bptr[N]; b10 = Bptr[2*N]; b11 = Bptr[3*N];

    // stage tile 0
    {
        uint32_t h, l;
        bf16_split_pack(av0.x, av0.y, h, l); Ah[0][k2a+0][ar] = h; Al[0][k2a+0][ar] = l;
        bf16_split_pack(av0.z, av0.w, h, l); Ah[0][k2a+1][ar] = h; Al[0][k2a+1][ar] = l;
        bf16_split_pack(av1.x, av1.y, h, l); Ah[0][k2a+2][ar] = h; Al[0][k2a+2][ar] = l;
        bf16_split_pack(av1.z, av1.w, h, l); Ah[0][k2a+3][ar] = h; Al[0][k2a+3][ar] = l;
        bf16_split_pack(b00, b01, h, l);     Bh[0][k2b  ][bn] = h; Bl[0][k2b  ][bn] = l;
        bf16_split_pack(b10, b11, h, l);     Bh[0][k2b+1][bn] = h; Bl[0][k2b+1][bn] = l;
    }

    int stage = 0;
    for (int k0 = 0; k0 < K; k0 += 16) {
        __syncthreads();
        bool more = (k0 + 16) < K;
        if (more) {
            av0 = *(const float4*)(Aptr + k0 + 16);
            av1 = *(const float4*)(Aptr + k0 + 20);
            const float* bp = Bptr + (size_t)(k0 + 16) * N;
            b00 = bp[0]; b01 = bp[N]; b10 = bp[2*N]; b11 = bp[3*N];
        }

        // fragments
        uint32_t ah[2][4], al[2][4], bh[4][2], blo[4][2];
#pragma unroll
        for (int mt = 0; mt < 2; mt++) {
            int r0 = mbase + mt*16 + g;
            ah[mt][0] = Ah[stage][t4  ][r0];   ah[mt][1] = Ah[stage][t4  ][r0+8];
            ah[mt][2] = Ah[stage][t4+4][r0];   ah[mt][3] = Ah[stage][t4+4][r0+8];
            al[mt][0] = Al[stage][t4  ][r0];   al[mt][1] = Al[stage][t4  ][r0+8];
            al[mt][2] = Al[stage][t4+4][r0];   al[mt][3] = Al[stage][t4+4][r0+8];
        }
#pragma unroll
        for (int nt = 0; nt < 4; nt++) {
            int cn = nbase + nt*8 + g;
            bh[nt][0]  = Bh[stage][t4][cn];    bh[nt][1]  = Bh[stage][t4+4][cn];
            blo[nt][0] = Bl[stage][t4][cn];    blo[nt][1] = Bl[stage][t4+4][cn];
        }
#pragma unroll
        for (int mt = 0; mt < 2; mt++)
#pragma unroll
            for (int nt = 0; nt < 4; nt++) {
                mma16(c[mt][nt], al[mt], bh[nt]);   // small terms first
                mma16(c[mt][nt], ah[mt], blo[nt]);
                mma16(c[mt][nt], ah[mt], bh[nt]);
            }

        if (more) {
            int ns = stage ^ 1;
            uint32_t h, l;
            bf16_split_pack(av0.x, av0.y, h, l); Ah[ns][k2a+0][ar] = h; Al[ns][k2a+0][ar] = l;
            bf16_split_pack(av0.z, av0.w, h, l); Ah[ns][k2a+1][ar] = h; Al[ns][k2a+1][ar] = l;
            bf16_split_pack(av1.x, av1.y, h, l); Ah[ns][k2a+2][ar] = h; Al[ns][k2a+2][ar] = l;
            bf16_split_pack(av1.z, av1.w, h, l); Ah[ns][k2a+3][ar] = h; Al[ns][k2a+3][ar] = l;
            bf16_split_pack(b00, b01, h, l);     Bh[ns][k2b  ][bn] = h; Bl[ns][k2b  ][bn] = l;
            bf16_split_pack(b10, b11, h, l);     Bh[ns][k2b+1][bn] = h; Bl[ns][k2b+1][bn] = l;
        }
        stage ^= 1;
    }

    // epilogue: bias -> (optional l2norm) -> (optional gelu) -> (optional res) -> store
#pragma unroll
    for (int mt = 0; mt < 2; mt++)
#pragma unroll
        for (int nt = 0; nt < 4; nt++) {
            int col = n0 + nbase + nt*8 + t4*2;
            float b0v = bias[col], b1v = bias[col + 1];
            c[mt][nt][0] += b0v; c[mt][nt][1] += b1v;
            c[mt][nt][2] += b0v; c[mt][nt][3] += b1v;
        }

    if (mode == 2) {
#pragma unroll
        for (int mt = 0; mt < 2; mt++) {
            float ss0 = 0.f, ss1 = 0.f;
#pragma unroll
            for (int nt = 0; nt < 4; nt++) {
                ss0 += c[mt][nt][0]*c[mt][nt][0] + c[mt][nt][1]*c[mt][nt][1];
                ss1 += c[mt][nt][2]*c[mt][nt][2] + c[mt][nt][3]*c[mt][nt][3];
            }
            ss0 += __shfl_xor_sync(~0u, ss0, 1); ss0 += __shfl_xor_sync(~0u, ss0, 2);
            ss1 += __shfl_xor_sync(~0u, ss1, 1); ss1 += __shfl_xor_sync(~0u, ss1, 2);
            float i0 = 1.f / fmaxf(sqrtf(ss0), 1e-6f);
            float i1 = 1.f / fmaxf(sqrtf(ss1), 1e-6f);
#pragma unroll
            for (int nt = 0; nt < 4; nt++) {
                c[mt][nt][0] *= i0; c[mt][nt][1] *= i0;
                c[mt][nt][2] *= i1; c[mt][nt][3] *= i1;
            }
        }
    }

#pragma unroll
    for (int mt = 0; mt < 2; mt++)
#pragma unroll
        for (int nt = 0; nt < 4; nt++) {
            int col = n0 + nbase + nt*8 + t4*2;
            size_t r0 = (size_t)(m0 + mbase + mt*16 + g);
            size_t r1 = r0 + 8;
            float v0 = c[mt][nt][0], v1 = c[mt][nt][1];
            float v2 = c[mt][nt][2], v3 = c[mt][nt][3];
            if (mode == 1) {
                v0 = 0.5f*v0*(1.f + erff(v0*0.70710678118654752f));
                v1 = 0.5f*v1*(1.f + erff(v1*0.70710678118654752f));
                v2 = 0.5f*v2*(1.f + erff(v2*0.70710678118654752f));
                v3 = 0.5f*v3*(1.f + erff(v3*0.70710678118654752f));
            }
            if (res) {
                v0 += res[r0*N + col]; v1 += res[r0*N + col + 1];
                v2 += res[r1*N + col]; v3 += res[r1*N + col + 1];
            }
            *(float2*)&C[r0*N + col] = make_float2(v0, v1);
            *(float2*)&C[r1*N + col] = make_float2(v2, v3);
        }
}

// ---------------- launch ----------------
extern "C" void kernel_launch(void* const* d_in, const int* in_sizes, int n_in,
                              void* d_out, int out_size) {
    const float* vis   = (const float*)d_in[0];
    const float* text  = (const float*)d_in[1];
    const float* Wq    = (const float*)d_in[2];
    const float* bq    = (const float*)d_in[3];
    const float* Wk    = (const float*)d_in[4];
    const float* bk    = (const float*)d_in[5];
    const float* Wv    = (const float*)d_in[6];
    const float* bv    = (const float*)d_in[7];
    const float* Wo    = (const float*)d_in[8];
    const float* bo    = (const float*)d_in[9];
    const float* g1    = (const float*)d_in[10];
    const float* b1    = (const float*)d_in[11];
    const float* g2    = (const float*)d_in[12];
    const float* b2    = (const float*)d_in[13];
    const float* Wf1   = (const float*)d_in[14];
    const float* bf1   = (const float*)d_in[15];
    const float* Wf2   = (const float*)d_in[16];
    const float* bf2   = (const float*)d_in[17];
    const float* ls    = (const float*)d_in[18];
    const float* alpha = (const float*)d_in[19];
    float* out = (float*)d_out;

    float *px, *pq, *paligned, *pproj, *py2, *phdn;
    cudaGetSymbolAddress((void**)&px,       g_x);
    cudaGetSymbolAddress((void**)&pq,       g_q);
    cudaGetSymbolAddress((void**)&paligned, g_aligned);
    cudaGetSymbolAddress((void**)&pproj,    g_proj);
    cudaGetSymbolAddress((void**)&py2,      g_y2);
    cudaGetSymbolAddress((void**)&phdn,     g_hdn);

    ln1_kernel<<<ROWS/8, 256>>>(vis, g1, b1);
    kv_kernel<<<NB*NT, 256>>>(text, Wk, bk, Wv, bv);
    gemm_bf16s_kernel<<<dim3(CVD/64, ROWS/128), 256>>>(px, Wq, bq, nullptr, pq, ROWS, CVD, CVD, 2);
    attn_kernel<<<ROWS, 256>>>(ls);
    gemm_bf16s_kernel<<<dim3(CVD/64, ROWS/128), 256>>>(paligned, Wo, bo, nullptr, pproj, ROWS, CVD, CVD, 0);
    ln2res_kernel<<<ROWS/8, 256>>>(g2, b2, alpha);
    gemm_bf16s_kernel<<<dim3(4*CVD/64, ROWS/128), 256>>>(py2, Wf1, bf1, nullptr, phdn, ROWS, 4*CVD, CVD, 1);
    gemm_bf16s_kernel<<<dim3(CVD/64, ROWS/128), 256>>>(phdn, Wf2, bf2, py2, out, ROWS, CVD, 4*CVD, 0);
}